// round 1
// baseline (speedup 1.0000x reference)
#include <cuda_runtime.h>
#include <math_constants.h>

// Problem constants (fixed shapes from setup_inputs)
#define B      32
#define C0     512
#define C1     1024
#define HW0    1444   // 38*38
#define HW1    361    // 19*19
#define THRESH 0.15f

// Output layout (float32): fw[2], embT0[B*HW0], embT1[B*HW1], embS0[B*HW0], embS1[B*HW1]
#define OFF_FW    0
#define OFF_ET0   2
#define OFF_ET1   (OFF_ET0 + B*HW0)
#define OFF_ES0   (OFF_ET1 + B*HW1)
#define OFF_ES1   (OFF_ES0 + B*HW0)

// Device scratch (no allocation allowed)
__device__ float d_w0[B * C0];
__device__ float d_w1[B * C1];
__device__ float d_cam0[B * HW0];
__device__ float d_cam1[B * HW1];
__device__ float d_bmax[2 * B];    // [level][b] pre-clamp max of cam
__device__ float d_score[2 * B];   // [level][b] mean of clipped cam

// ---------------------------------------------------------------------------
// Stage 1: w[b,c] = mean over HW of g[b,c,:,:].  One warp per (b,c) row.
// ---------------------------------------------------------------------------
__global__ void k_gmean(const float* __restrict__ g, float* __restrict__ w,
                        int rows, int HW, float invHW) {
    int row  = blockIdx.x * (blockDim.x >> 5) + (threadIdx.x >> 5);
    int lane = threadIdx.x & 31;
    if (row >= rows) return;
    const float* p = g + (size_t)row * HW;
    float s = 0.f;
    for (int i = lane; i < HW; i += 32) s += p[i];
    #pragma unroll
    for (int o = 16; o; o >>= 1) s += __shfl_xor_sync(0xffffffffu, s, o);
    if (lane == 0) w[row] = s * invHW;
}

// ---------------------------------------------------------------------------
// Stage 2: per pixel (b,hw): cam = sum_c w[b,c]*Tf, meanT = mean_c Tf,
// meanS = mean_c Sf.  Block = 256 threads = 4 channel-groups x 64 hw-lanes.
// Deterministic: fixed-order combine of the 4 partials.
// Channel means are written straight into d_out; mask zeroing comes later.
// ---------------------------------------------------------------------------
template <int C, int HW>
__global__ void k_cam(const float* __restrict__ Tf, const float* __restrict__ Sf,
                      const float* __restrict__ w,
                      float* __restrict__ cam,
                      float* __restrict__ outT, float* __restrict__ outS) {
    __shared__ float sw[C];
    __shared__ float pc[4][64], pt[4][64], ps[4][64];

    const int b   = blockIdx.y;
    const int hwl = threadIdx.x & 63;
    const int cg  = threadIdx.x >> 6;            // 0..3
    const int hw  = blockIdx.x * 64 + hwl;

    for (int c = threadIdx.x; c < C; c += 256) sw[c] = w[b * C + c];
    __syncthreads();

    float acc_c = 0.f, acc_t = 0.f, acc_s = 0.f;
    if (hw < HW) {
        const float* tp = Tf + (size_t)b * C * HW + hw;
        const float* sp = Sf + (size_t)b * C * HW + hw;
        const int cpg = C / 4;
        const int c0  = cg * cpg;
        #pragma unroll 8
        for (int c = c0; c < c0 + cpg; ++c) {
            float t = tp[(size_t)c * HW];
            float s = sp[(size_t)c * HW];
            acc_c = fmaf(sw[c], t, acc_c);
            acc_t += t;
            acc_s += s;
        }
    }
    pc[cg][hwl] = acc_c; pt[cg][hwl] = acc_t; ps[cg][hwl] = acc_s;
    __syncthreads();

    if (cg == 0 && hw < HW) {
        float cc = (pc[0][hwl] + pc[1][hwl]) + (pc[2][hwl] + pc[3][hwl]);
        float tt = (pt[0][hwl] + pt[1][hwl]) + (pt[2][hwl] + pt[3][hwl]);
        float ss = (ps[0][hwl] + ps[1][hwl]) + (ps[2][hwl] + ps[3][hwl]);
        const float invC = 1.f / (float)C;
        size_t o = (size_t)b * HW + hw;
        cam[o]  = cc;
        outT[o] = tt * invC;
        outS[o] = ss * invC;
    }
}

// ---------------------------------------------------------------------------
// Stage 3: per-batch max (pre-clamp) and clipped mean of cam.
// One block (256 thr) per batch sample. Deterministic smem tree reduce.
// ---------------------------------------------------------------------------
__global__ void k_stats(const float* __restrict__ cam, float* __restrict__ bmax,
                        float* __restrict__ score, int HW, float invHW) {
    const int b = blockIdx.x;
    const int t = threadIdx.x;
    const float* p = cam + (size_t)b * HW;
    float mx = -CUDART_INF_F, sm = 0.f;
    for (int i = t; i < HW; i += 256) {
        float v = p[i];
        mx = fmaxf(mx, v);
        sm += fmaxf(v, 0.f);
    }
    __shared__ float smx[256], ssm[256];
    smx[t] = mx; ssm[t] = sm;
    __syncthreads();
    #pragma unroll
    for (int s = 128; s; s >>= 1) {
        if (t < s) { smx[t] = fmaxf(smx[t], smx[t + s]); ssm[t] += ssm[t + s]; }
        __syncthreads();
    }
    if (t == 0) { bmax[b] = smx[0]; score[b] = ssm[0] * invHW; }
}

// ---------------------------------------------------------------------------
// Stage 4: fw = normalize([sum_b s0, sum_b s1]); write d_out[0..1].
// ---------------------------------------------------------------------------
__global__ void k_fw(const float* __restrict__ score, float* __restrict__ out) {
    if (threadIdx.x == 0) {
        float s0 = 0.f, s1 = 0.f;
        for (int i = 0; i < B; ++i) { s0 += score[i]; s1 += score[B + i]; }
        float inv = 1.f / (s0 + s1);
        out[0] = s0 * inv;
        out[1] = s1 * inv;
    }
}

// ---------------------------------------------------------------------------
// Stage 5: zero emb positions where mask fails (cam <= |0.15*max|).
// ---------------------------------------------------------------------------
__global__ void k_mask(const float* __restrict__ cam, const float* __restrict__ bmax,
                       float* __restrict__ outT, float* __restrict__ outS,
                       int HW, int n) {
    int i = blockIdx.x * blockDim.x + threadIdx.x;
    if (i >= n) return;
    int b = i / HW;
    float thr = fabsf(bmax[b] * THRESH);
    if (!(cam[i] > thr)) { outT[i] = 0.f; outS[i] = 0.f; }
}

// ---------------------------------------------------------------------------
extern "C" void kernel_launch(void* const* d_in, const int* in_sizes, int n_in,
                              void* d_out, int out_size) {
    const float* Tf0 = (const float*)d_in[0];
    const float* Tf1 = (const float*)d_in[1];
    const float* Sf0 = (const float*)d_in[2];
    const float* Sf1 = (const float*)d_in[3];
    const float* g0  = (const float*)d_in[4];
    const float* g1  = (const float*)d_in[5];
    float* out = (float*)d_out;

    float *w0, *w1, *cam0, *cam1, *bmax, *score;
    cudaGetSymbolAddress((void**)&w0,    d_w0);
    cudaGetSymbolAddress((void**)&w1,    d_w1);
    cudaGetSymbolAddress((void**)&cam0,  d_cam0);
    cudaGetSymbolAddress((void**)&cam1,  d_cam1);
    cudaGetSymbolAddress((void**)&bmax,  d_bmax);
    cudaGetSymbolAddress((void**)&score, d_score);

    // Stage 1: GradCAM weights
    {
        int rows0 = B * C0, rows1 = B * C1;
        k_gmean<<<(rows0 + 7) / 8, 256>>>(g0, w0, rows0, HW0, 1.f / HW0);
        k_gmean<<<(rows1 + 7) / 8, 256>>>(g1, w1, rows1, HW1, 1.f / HW1);
    }

    // Stage 2: cam + channel means (means written straight into d_out)
    {
        dim3 g0d((HW0 + 63) / 64, B);
        dim3 g1d((HW1 + 63) / 64, B);
        k_cam<C0, HW0><<<g0d, 256>>>(Tf0, Sf0, w0, cam0,
                                     out + OFF_ET0, out + OFF_ES0);
        k_cam<C1, HW1><<<g1d, 256>>>(Tf1, Sf1, w1, cam1,
                                     out + OFF_ET1, out + OFF_ES1);
    }

    // Stage 3: per-batch max + score
    k_stats<<<B, 256>>>(cam0, bmax,     score,     HW0, 1.f / HW0);
    k_stats<<<B, 256>>>(cam1, bmax + B, score + B, HW1, 1.f / HW1);

    // Stage 4: feature weights
    k_fw<<<1, 32>>>(score, out + OFF_FW);

    // Stage 5: apply masks in place on d_out
    {
        int n0 = B * HW0, n1 = B * HW1;
        k_mask<<<(n0 + 255) / 256, 256>>>(cam0, bmax,
                                          out + OFF_ET0, out + OFF_ES0, HW0, n0);
        k_mask<<<(n1 + 255) / 256, 256>>>(cam1, bmax + B,
                                          out + OFF_ET1, out + OFF_ES1, HW1, n1);
    }
}

// round 2
// speedup vs baseline: 1.1384x; 1.1384x over previous
#include <cuda_runtime.h>
#include <math_constants.h>

// Fixed shapes
#define B      32
#define C0     512
#define C1     1024
#define HW0    1444   // 38*38
#define HW1    361    // 19*19
#define THRESH 0.15f
#define NCH0   4      // channel chunks, level 0
#define NCH1   8      // channel chunks, level 1

// Output layout (float32): fw[2], embT0, embT1, embS0, embS1
#define OFF_FW  0
#define OFF_ET0 2
#define OFF_ET1 (OFF_ET0 + B*HW0)
#define OFF_ES0 (OFF_ET1 + B*HW1)
#define OFF_ES1 (OFF_ES0 + B*HW0)

// Device scratch (static; no allocation allowed)
__device__ float d_w0[B * C0];
__device__ float d_w1[B * C1];
__device__ float d_pc0[NCH0 * B * HW0];
__device__ float d_pt0[NCH0 * B * HW0];
__device__ float d_ps0[NCH0 * B * HW0];
__device__ float d_pc1[NCH1 * B * HW1];
__device__ float d_pt1[NCH1 * B * HW1];
__device__ float d_ps1[NCH1 * B * HW1];
__device__ float d_score[2 * B];

// ---------------------------------------------------------------------------
// Stage 1: w[b,c] = mean over HW of g. One warp per (b,c) row.
// Vectorized float4 variant for HW divisible by 4 with 16B-aligned rows.
// ---------------------------------------------------------------------------
__global__ void k_gmean4(const float* __restrict__ g, float* __restrict__ w,
                         int rows, int HW4, float invHW) {
    int row  = blockIdx.x * (blockDim.x >> 5) + (threadIdx.x >> 5);
    int lane = threadIdx.x & 31;
    if (row >= rows) return;
    const float4* p = reinterpret_cast<const float4*>(g) + (size_t)row * HW4;
    float s = 0.f;
    for (int i = lane; i < HW4; i += 32) {
        float4 v = p[i];
        s += (v.x + v.y) + (v.z + v.w);
    }
    #pragma unroll
    for (int o = 16; o; o >>= 1) s += __shfl_xor_sync(0xffffffffu, s, o);
    if (lane == 0) w[row] = s * invHW;
}

__global__ void k_gmean(const float* __restrict__ g, float* __restrict__ w,
                        int rows, int HW, float invHW) {
    int row  = blockIdx.x * (blockDim.x >> 5) + (threadIdx.x >> 5);
    int lane = threadIdx.x & 31;
    if (row >= rows) return;
    const float* p = g + (size_t)row * HW;
    float s = 0.f;
    #pragma unroll 4
    for (int i = lane; i < HW; i += 32) s += p[i];
    #pragma unroll
    for (int o = 16; o; o >>= 1) s += __shfl_xor_sync(0xffffffffu, s, o);
    if (lane == 0) w[row] = s * invHW;
}

// ---------------------------------------------------------------------------
// Stage 2: partial cam / sumT / sumS per channel-chunk.
// Block = 256 threads = 128 hw lanes x 2 channel groups.
// grid = (hw_blocks, B, CHUNKS).  Deterministic fixed-order combine.
// ---------------------------------------------------------------------------
template <int C, int HW, int CHUNKS>
__global__ void k_cam_part(const float* __restrict__ Tf, const float* __restrict__ Sf,
                           const float* __restrict__ w,
                           float* __restrict__ pc, float* __restrict__ pt,
                           float* __restrict__ ps) {
    constexpr int CPC = C / CHUNKS;   // channels per chunk
    constexpr int CPG = CPC / 2;      // channels per group
    __shared__ float sw[CPC];
    __shared__ float rc[2][128], rt[2][128], rs[2][128];

    const int b     = blockIdx.y;
    const int chunk = blockIdx.z;
    const int hwl   = threadIdx.x & 127;
    const int cg    = threadIdx.x >> 7;      // 0..1
    const int hw    = blockIdx.x * 128 + hwl;
    const int cbase = chunk * CPC;

    for (int i = threadIdx.x; i < CPC; i += 256) sw[i] = w[b * C + cbase + i];
    __syncthreads();

    float ac = 0.f, at = 0.f, as_ = 0.f;
    if (hw < HW) {
        const float* tp = Tf + ((size_t)b * C + cbase + cg * CPG) * HW + hw;
        const float* sp = Sf + ((size_t)b * C + cbase + cg * CPG) * HW + hw;
        const float* wp = sw + cg * CPG;
        #pragma unroll 16
        for (int c = 0; c < CPG; ++c) {
            float t = tp[(size_t)c * HW];
            float s = sp[(size_t)c * HW];
            ac = fmaf(wp[c], t, ac);
            at += t;
            as_ += s;
        }
    }
    rc[cg][hwl] = ac; rt[cg][hwl] = at; rs[cg][hwl] = as_;
    __syncthreads();

    if (cg == 0 && hw < HW) {
        size_t o = ((size_t)chunk * B + b) * HW + hw;
        pc[o] = rc[0][hwl] + rc[1][hwl];
        pt[o] = rt[0][hwl] + rt[1][hwl];
        ps[o] = rs[0][hwl] + rs[1][hwl];
    }
}

// ---------------------------------------------------------------------------
// Stage 3 (fused combine + stats + mask): one block per batch sample.
// Combines chunk partials in fixed order, computes pre-clamp max & clipped
// mean (score), then masks & writes emb outputs.
// ---------------------------------------------------------------------------
template <int C, int HW, int CHUNKS>
__global__ void k_finish(const float* __restrict__ pc, const float* __restrict__ pt,
                         const float* __restrict__ ps,
                         float* __restrict__ outT, float* __restrict__ outS,
                         float* __restrict__ score) {
    constexpr int PPT  = (HW + 255) / 256;
    constexpr float invC  = 1.f / (float)C;
    constexpr float invHW = 1.f / (float)HW;
    const int b = blockIdx.x;
    const int t = threadIdx.x;

    float camv[PPT], tv[PPT], sv[PPT];
    float mx = -CUDART_INF_F, sm = 0.f;

    #pragma unroll
    for (int p = 0; p < PPT; ++p) {
        int i = p * 256 + t;
        camv[p] = 0.f; tv[p] = 0.f; sv[p] = 0.f;
        if (i < HW) {
            float cc = 0.f, tt = 0.f, ss = 0.f;
            #pragma unroll
            for (int ch = 0; ch < CHUNKS; ++ch) {
                size_t o = ((size_t)ch * B + b) * HW + i;
                cc += pc[o]; tt += pt[o]; ss += ps[o];
            }
            camv[p] = cc;
            tv[p]   = tt * invC;
            sv[p]   = ss * invC;
            mx = fmaxf(mx, cc);
            sm += fmaxf(cc, 0.f);
        }
    }

    __shared__ float smx[256], ssm[256];
    __shared__ float sthr;
    smx[t] = mx; ssm[t] = sm;
    __syncthreads();
    #pragma unroll
    for (int s = 128; s; s >>= 1) {
        if (t < s) { smx[t] = fmaxf(smx[t], smx[t + s]); ssm[t] += ssm[t + s]; }
        __syncthreads();
    }
    if (t == 0) {
        score[b] = ssm[0] * invHW;
        sthr = fabsf(smx[0] * THRESH);
    }
    __syncthreads();
    float thr = sthr;

    #pragma unroll
    for (int p = 0; p < PPT; ++p) {
        int i = p * 256 + t;
        if (i < HW) {
            bool m = camv[p] > thr;
            size_t o = (size_t)b * HW + i;
            outT[o] = m ? tv[p] : 0.f;
            outS[o] = m ? sv[p] : 0.f;
        }
    }
}

// ---------------------------------------------------------------------------
// Stage 4: feature weights -> d_out[0..1]
// ---------------------------------------------------------------------------
__global__ void k_fw(const float* __restrict__ score, float* __restrict__ out) {
    if (threadIdx.x == 0) {
        float s0 = 0.f, s1 = 0.f;
        for (int i = 0; i < B; ++i) { s0 += score[i]; s1 += score[B + i]; }
        float inv = 1.f / (s0 + s1);
        out[0] = s0 * inv;
        out[1] = s1 * inv;
    }
}

// ---------------------------------------------------------------------------
extern "C" void kernel_launch(void* const* d_in, const int* in_sizes, int n_in,
                              void* d_out, int out_size) {
    const float* Tf0 = (const float*)d_in[0];
    const float* Tf1 = (const float*)d_in[1];
    const float* Sf0 = (const float*)d_in[2];
    const float* Sf1 = (const float*)d_in[3];
    const float* g0  = (const float*)d_in[4];
    const float* g1  = (const float*)d_in[5];
    float* out = (float*)d_out;

    float *w0, *w1, *pc0, *pt0, *ps0, *pc1, *pt1, *ps1, *score;
    cudaGetSymbolAddress((void**)&w0,  d_w0);
    cudaGetSymbolAddress((void**)&w1,  d_w1);
    cudaGetSymbolAddress((void**)&pc0, d_pc0);
    cudaGetSymbolAddress((void**)&pt0, d_pt0);
    cudaGetSymbolAddress((void**)&ps0, d_ps0);
    cudaGetSymbolAddress((void**)&pc1, d_pc1);
    cudaGetSymbolAddress((void**)&pt1, d_pt1);
    cudaGetSymbolAddress((void**)&ps1, d_ps1);
    cudaGetSymbolAddress((void**)&score, d_score);

    // Stage 1: GradCAM weights
    {
        int rows0 = B * C0, rows1 = B * C1;
        // HW0 = 1444 = 4*361, rows 16B-aligned -> float4 path
        k_gmean4<<<(rows0 + 7) / 8, 256>>>(g0, w0, rows0, HW0 / 4, 1.f / HW0);
        k_gmean <<<(rows1 + 7) / 8, 256>>>(g1, w1, rows1, HW1, 1.f / HW1);
    }

    // Stage 2: chunked partial cam / channel sums
    {
        dim3 grid0((HW0 + 127) / 128, B, NCH0);   // 12 x 32 x 4 = 1536 blocks
        dim3 grid1((HW1 + 127) / 128, B, NCH1);   //  3 x 32 x 8 =  768 blocks
        k_cam_part<C0, HW0, NCH0><<<grid0, 256>>>(Tf0, Sf0, w0, pc0, pt0, ps0);
        k_cam_part<C1, HW1, NCH1><<<grid1, 256>>>(Tf1, Sf1, w1, pc1, pt1, ps1);
    }

    // Stage 3: combine + stats + mask (fused), one block per sample
    k_finish<C0, HW0, NCH0><<<B, 256>>>(pc0, pt0, ps0,
                                        out + OFF_ET0, out + OFF_ES0, score);
    k_finish<C1, HW1, NCH1><<<B, 256>>>(pc1, pt1, ps1,
                                        out + OFF_ET1, out + OFF_ES1, score + B);

    // Stage 4: feature weights
    k_fw<<<1, 32>>>(score, out + OFF_FW);
}

// round 3
// speedup vs baseline: 1.3012x; 1.1430x over previous
#include <cuda_runtime.h>
#include <math_constants.h>

// Fixed shapes
#define B      32
#define C0     512
#define C1     1024
#define HW0    1444      // 38*38, divisible by 4
#define HW4_0  361       // HW0/4 in float4 units
#define HW1    361       // 19*19
#define THRESH 0.15f
#define NCH0   8         // channel chunks, level 0 (CPC0 = 64)
#define NCH1   16        // channel chunks, level 1 (CPC1 = 64)
#define CPC0   (C0/NCH0) // 64
#define CPG0   (CPC0/2)  // 32
#define CPC1   (C1/NCH1) // 64
#define CPG1   (CPC1/2)  // 32

// Output layout (float32): fw[2], embT0, embT1, embS0, embS1
#define OFF_FW  0
#define OFF_ET0 2
#define OFF_ET1 (OFF_ET0 + B*HW0)
#define OFF_ES0 (OFF_ET1 + B*HW1)
#define OFF_ES1 (OFF_ES0 + B*HW0)

// Static device scratch
__device__ float d_w0[B * C0];
__device__ float d_w1[B * C1];
__device__ float d_pc0[NCH0 * B * HW0];
__device__ float d_pt0[NCH0 * B * HW0];
__device__ float d_ps0[NCH0 * B * HW0];
__device__ float d_pc1[NCH1 * B * HW1];
__device__ float d_pt1[NCH1 * B * HW1];
__device__ float d_ps1[NCH1 * B * HW1];
__device__ float d_score[2 * B];
__device__ int   d_cnt = 0;

// ---------------------------------------------------------------------------
// Stage 1 (single launch, both levels): w[b,c] = mean_hw g[b,c,:,:].
// One warp per row. Level 0 uses float4 (rows 16B aligned), level 1 scalar.
// Blocks [0,2048): level 0 (16384 rows). Blocks [2048,6144): level 1 (32768).
// ---------------------------------------------------------------------------
__global__ void k_gmean_all(const float* __restrict__ g0,
                            const float* __restrict__ g1,
                            float* __restrict__ w0, float* __restrict__ w1) {
    const int lane = threadIdx.x & 31;
    const int wIdx = blockIdx.x * 8 + (threadIdx.x >> 5);
    if (blockIdx.x < 2048) {
        // level 0: float4 row reduce
        const float4* p = reinterpret_cast<const float4*>(g0) + (size_t)wIdx * HW4_0;
        float s = 0.f;
        for (int i = lane; i < HW4_0; i += 32) {
            float4 v = p[i];
            s += (v.x + v.y) + (v.z + v.w);
        }
        #pragma unroll
        for (int o = 16; o; o >>= 1) s += __shfl_xor_sync(0xffffffffu, s, o);
        if (lane == 0) w0[wIdx] = s * (1.f / HW0);
    } else {
        const int row = wIdx - 16384;
        const float* p = g1 + (size_t)row * HW1;
        float s = 0.f;
        #pragma unroll 4
        for (int i = lane; i < HW1; i += 32) s += p[i];
        #pragma unroll
        for (int o = 16; o; o >>= 1) s += __shfl_xor_sync(0xffffffffu, s, o);
        if (lane == 0) w1[row] = s * (1.f / HW1);
    }
}

// ---------------------------------------------------------------------------
// Stage 2 (single launch, both levels): per channel-chunk partial
// cam / sumT / sumS.  grid = (3, B, NCH0 + NCH1), block = 256.
// z < NCH0 -> level-0 chunk (float4 path); else level-1 chunk (scalar).
// Block = 128 hw lanes x 2 channel groups; fixed-order combine.
// ---------------------------------------------------------------------------
__global__ __launch_bounds__(256)
void k_cam_all(const float* __restrict__ Tf0, const float* __restrict__ Sf0,
               const float* __restrict__ w0,
               float* __restrict__ pc0, float* __restrict__ pt0, float* __restrict__ ps0,
               const float* __restrict__ Tf1, const float* __restrict__ Sf1,
               const float* __restrict__ w1,
               float* __restrict__ pc1, float* __restrict__ pt1, float* __restrict__ ps1) {
    __shared__ float  sw[64];
    __shared__ float4 red4[3][2][128];   // 12 KB; reused as float[] for level 1

    const int b   = blockIdx.y;
    const int z   = blockIdx.z;
    const int hwl = threadIdx.x & 127;
    const int cg  = threadIdx.x >> 7;    // 0..1

    if (z < NCH0) {
        // ----- level 0: float4 along hw -----
        const int chunk = z;
        for (int i = threadIdx.x; i < CPC0; i += 256)
            sw[i] = w0[b * C0 + chunk * CPC0 + i];
        __syncthreads();

        const int q = blockIdx.x * 128 + hwl;   // float4 index within row
        float4 ac = {0,0,0,0}, at = {0,0,0,0}, as4 = {0,0,0,0};
        if (q < HW4_0) {
            const size_t rb = (size_t)(b * C0 + chunk * CPC0 + cg * CPG0) * HW4_0 + q;
            const float4* tp = reinterpret_cast<const float4*>(Tf0) + rb;
            const float4* sp = reinterpret_cast<const float4*>(Sf0) + rb;
            const float*  wp = sw + cg * CPG0;
            #pragma unroll 8
            for (int c = 0; c < CPG0; ++c) {
                float4 t = tp[(size_t)c * HW4_0];
                float4 s = sp[(size_t)c * HW4_0];
                float  wv = wp[c];
                ac.x = fmaf(wv, t.x, ac.x); ac.y = fmaf(wv, t.y, ac.y);
                ac.z = fmaf(wv, t.z, ac.z); ac.w = fmaf(wv, t.w, ac.w);
                at.x += t.x; at.y += t.y; at.z += t.z; at.w += t.w;
                as4.x += s.x; as4.y += s.y; as4.z += s.z; as4.w += s.w;
            }
        }
        red4[0][cg][hwl] = ac; red4[1][cg][hwl] = at; red4[2][cg][hwl] = as4;
        __syncthreads();

        if (cg == 0 && q < HW4_0) {
            float4 a0 = red4[0][0][hwl], a1 = red4[0][1][hwl];
            float4 t0 = red4[1][0][hwl], t1 = red4[1][1][hwl];
            float4 s0 = red4[2][0][hwl], s1 = red4[2][1][hwl];
            float4 cc = {a0.x+a1.x, a0.y+a1.y, a0.z+a1.z, a0.w+a1.w};
            float4 tt = {t0.x+t1.x, t0.y+t1.y, t0.z+t1.z, t0.w+t1.w};
            float4 ss = {s0.x+s1.x, s0.y+s1.y, s0.z+s1.z, s0.w+s1.w};
            const size_t o = (size_t)(chunk * B + b) * HW4_0 + q;
            reinterpret_cast<float4*>(pc0)[o] = cc;
            reinterpret_cast<float4*>(pt0)[o] = tt;
            reinterpret_cast<float4*>(ps0)[o] = ss;
        }
    } else {
        // ----- level 1: scalar along hw -----
        const int chunk = z - NCH0;
        for (int i = threadIdx.x; i < CPC1; i += 256)
            sw[i] = w1[b * C1 + chunk * CPC1 + i];
        __syncthreads();

        const int hw = blockIdx.x * 128 + hwl;
        float ac = 0.f, at = 0.f, as_ = 0.f;
        if (hw < HW1) {
            const size_t rb = (size_t)(b * C1 + chunk * CPC1 + cg * CPG1) * HW1 + hw;
            const float* tp = Tf1 + rb;
            const float* sp = Sf1 + rb;
            const float* wp = sw + cg * CPG1;
            #pragma unroll 16
            for (int c = 0; c < CPG1; ++c) {
                float t = tp[(size_t)c * HW1];
                float s = sp[(size_t)c * HW1];
                ac = fmaf(wp[c], t, ac);
                at += t;
                as_ += s;
            }
        }
        float* red = reinterpret_cast<float*>(red4);  // [3][2][128] floats
        red[(0*2 + cg)*128 + hwl] = ac;
        red[(1*2 + cg)*128 + hwl] = at;
        red[(2*2 + cg)*128 + hwl] = as_;
        __syncthreads();

        if (cg == 0 && hw < HW1) {
            float cc = red[0*256 + hwl] + red[0*256 + 128 + hwl];
            float tt = red[1*256 + hwl] + red[1*256 + 128 + hwl];
            float ss = red[2*256 + hwl] + red[2*256 + 128 + hwl];
            const size_t o = (size_t)(chunk * B + b) * HW1 + hw;
            pc1[o] = cc; pt1[o] = tt; ps1[o] = ss;
        }
    }
}

// ---------------------------------------------------------------------------
// Stage 3 (single launch): combine chunks + stats + mask + (last block) fw.
// grid = 64 blocks (32 per level), 512 threads.
// ---------------------------------------------------------------------------
template <int C, int HW, int CHUNKS, int PPT>
__device__ __forceinline__
void finish_impl(const float* __restrict__ pc, const float* __restrict__ pt,
                 const float* __restrict__ ps,
                 float* __restrict__ outT, float* __restrict__ outS,
                 float* __restrict__ score_slot, int b,
                 float* smx, float* ssm, float* sthr) {
    constexpr float invC  = 1.f / (float)C;
    constexpr float invHW = 1.f / (float)HW;
    const int t = threadIdx.x;

    float camv[PPT], tv[PPT], sv[PPT];
    float mx = -CUDART_INF_F, sm = 0.f;

    #pragma unroll
    for (int p = 0; p < PPT; ++p) {
        const int i = p * 512 + t;
        camv[p] = 0.f; tv[p] = 0.f; sv[p] = 0.f;
        if (i < HW) {
            float cc = 0.f, tt = 0.f, ss = 0.f;
            #pragma unroll
            for (int ch = 0; ch < CHUNKS; ++ch) {
                const size_t o = (size_t)(ch * B + b) * HW + i;
                cc += pc[o]; tt += pt[o]; ss += ps[o];
            }
            camv[p] = cc;
            tv[p]   = tt * invC;
            sv[p]   = ss * invC;
            mx = fmaxf(mx, cc);
            sm += fmaxf(cc, 0.f);
        }
    }

    smx[t] = mx; ssm[t] = sm;
    __syncthreads();
    #pragma unroll
    for (int s = 256; s; s >>= 1) {
        if (t < s) { smx[t] = fmaxf(smx[t], smx[t + s]); ssm[t] += ssm[t + s]; }
        __syncthreads();
    }
    if (t == 0) {
        *score_slot = ssm[0] * invHW;
        *sthr = fabsf(smx[0] * THRESH);
    }
    __syncthreads();
    const float thr = *sthr;

    #pragma unroll
    for (int p = 0; p < PPT; ++p) {
        const int i = p * 512 + t;
        if (i < HW) {
            const bool m = camv[p] > thr;
            const size_t o = (size_t)b * HW + i;
            outT[o] = m ? tv[p] : 0.f;
            outS[o] = m ? sv[p] : 0.f;
        }
    }
}

__global__ __launch_bounds__(512)
void k_finish_all(const float* __restrict__ pc0, const float* __restrict__ pt0,
                  const float* __restrict__ ps0,
                  const float* __restrict__ pc1, const float* __restrict__ pt1,
                  const float* __restrict__ ps1,
                  float* __restrict__ out, float* __restrict__ score) {
    __shared__ float smx[512], ssm[512], sthr;

    if (blockIdx.x < 32) {
        const int b = blockIdx.x;
        finish_impl<C0, HW0, NCH0, 3>(pc0, pt0, ps0,
                                      out + OFF_ET0, out + OFF_ES0,
                                      score + b, b, smx, ssm, &sthr);
    } else {
        const int b = blockIdx.x - 32;
        finish_impl<C1, HW1, NCH1, 1>(pc1, pt1, ps1,
                                      out + OFF_ET1, out + OFF_ES1,
                                      score + B + b, b, smx, ssm, &sthr);
    }

    // Last block computes feature weights (threadfence + atomic pattern).
    if (threadIdx.x == 0) {
        __threadfence();
        const int old = atomicAdd(&d_cnt, 1);
        if (old == 63) {
            __threadfence();
            float s0 = 0.f, s1 = 0.f;
            for (int i = 0; i < B; ++i) { s0 += score[i]; s1 += score[B + i]; }
            const float inv = 1.f / (s0 + s1);
            out[OFF_FW + 0] = s0 * inv;
            out[OFF_FW + 1] = s1 * inv;
            d_cnt = 0;   // reset for graph replay determinism
        }
    }
}

// ---------------------------------------------------------------------------
extern "C" void kernel_launch(void* const* d_in, const int* in_sizes, int n_in,
                              void* d_out, int out_size) {
    const float* Tf0 = (const float*)d_in[0];
    const float* Tf1 = (const float*)d_in[1];
    const float* Sf0 = (const float*)d_in[2];
    const float* Sf1 = (const float*)d_in[3];
    const float* g0  = (const float*)d_in[4];
    const float* g1  = (const float*)d_in[5];
    float* out = (float*)d_out;

    float *w0, *w1, *pc0, *pt0, *ps0, *pc1, *pt1, *ps1, *score;
    cudaGetSymbolAddress((void**)&w0,  d_w0);
    cudaGetSymbolAddress((void**)&w1,  d_w1);
    cudaGetSymbolAddress((void**)&pc0, d_pc0);
    cudaGetSymbolAddress((void**)&pt0, d_pt0);
    cudaGetSymbolAddress((void**)&ps0, d_ps0);
    cudaGetSymbolAddress((void**)&pc1, d_pc1);
    cudaGetSymbolAddress((void**)&pt1, d_pt1);
    cudaGetSymbolAddress((void**)&ps1, d_ps1);
    cudaGetSymbolAddress((void**)&score, d_score);

    // Stage 1: GradCAM weights, both levels in one launch
    k_gmean_all<<<6144, 256>>>(g0, g1, w0, w1);

    // Stage 2: chunked partial cam / channel sums, both levels in one launch
    {
        dim3 grid(3, B, NCH0 + NCH1);   // 3 x 32 x 24 = 2304 blocks
        k_cam_all<<<grid, 256>>>(Tf0, Sf0, w0, pc0, pt0, ps0,
                                 Tf1, Sf1, w1, pc1, pt1, ps1);
    }

    // Stage 3: combine + stats + mask + fw, one launch
    k_finish_all<<<64, 512>>>(pc0, pt0, ps0, pc1, pt1, ps1, out, score);
}

// round 4
// speedup vs baseline: 1.4235x; 1.0939x over previous
#include <cuda_runtime.h>
#include <math_constants.h>

// Fixed shapes
#define B      32
#define C0     512
#define C1     1024
#define HW0    1444      // 38*38, divisible by 4
#define HW4_0  361       // HW0/4 in float4 units
#define HW1    361       // 19*19
#define THRESH 0.15f
#define NCH0   8         // channel chunks, level 0 (CPC0 = 64)
#define NCH1   16        // channel chunks, level 1 (CPC1 = 64)
#define CPC0   (C0/NCH0) // 64
#define CPG0   (CPC0/2)  // 32
#define CPC1   (C1/NCH1) // 64
#define CPG1   (CPC1/2)  // 32

// Output layout (float32): fw[2], embT0, embT1, embS0, embS1
#define OFF_FW  0
#define OFF_ET0 2
#define OFF_ET1 (OFF_ET0 + B*HW0)
#define OFF_ES0 (OFF_ET1 + B*HW1)
#define OFF_ES1 (OFF_ES0 + B*HW0)

// Static device scratch
__device__ float d_w0[B * C0];
__device__ float d_w1[B * C1];
__device__ float d_pc0[NCH0 * B * HW0];
__device__ float d_pt0[NCH0 * B * HW0];
__device__ float d_ps0[NCH0 * B * HW0];
__device__ float d_pc1[NCH1 * B * HW1];
__device__ float d_pt1[NCH1 * B * HW1];
__device__ float d_ps1[NCH1 * B * HW1];
__device__ float d_score[2 * B];
__device__ int   d_cnt = 0;

// ---------------------------------------------------------------------------
// Stage 1: w[b,c] = mean_hw g[b,c,:,:], both levels, one launch.
// Level 0 (blocks [0,1024)): 2 rows per warp, float4 loads (rows 16B-aligned).
// Level 1 (blocks [1024,2048)): 4 rows per warp, scalar loads.
// Interleaved independent loads -> 4-8 LDGs in flight per thread.
// ---------------------------------------------------------------------------
__global__ __launch_bounds__(256)
void k_gmean_all(const float* __restrict__ g0, const float* __restrict__ g1,
                 float* __restrict__ w0, float* __restrict__ w1) {
    const int lane = threadIdx.x & 31;
    const int warp = threadIdx.x >> 5;

    if (blockIdx.x < 1024) {
        // level 0: 8192 row-pairs total
        const int pair = blockIdx.x * 8 + warp;
        const float4* p0 = reinterpret_cast<const float4*>(g0) + (size_t)(2 * pair) * HW4_0;
        const float4* p1 = p0 + HW4_0;
        float4 a0 = {0,0,0,0}, a1 = {0,0,0,0};
        #pragma unroll 2
        for (int i = lane; i < HW4_0; i += 32) {
            float4 v0 = __ldcs(p0 + i);
            float4 v1 = __ldcs(p1 + i);
            a0.x += v0.x; a0.y += v0.y; a0.z += v0.z; a0.w += v0.w;
            a1.x += v1.x; a1.y += v1.y; a1.z += v1.z; a1.w += v1.w;
        }
        float s0 = (a0.x + a0.y) + (a0.z + a0.w);
        float s1 = (a1.x + a1.y) + (a1.z + a1.w);
        #pragma unroll
        for (int o = 16; o; o >>= 1) {
            s0 += __shfl_xor_sync(0xffffffffu, s0, o);
            s1 += __shfl_xor_sync(0xffffffffu, s1, o);
        }
        if (lane == 0) {
            w0[2 * pair]     = s0 * (1.f / HW0);
            w0[2 * pair + 1] = s1 * (1.f / HW0);
        }
    } else {
        // level 1: 8192 row-quads total
        const int quad = (blockIdx.x - 1024) * 8 + warp;
        const float* p = g1 + (size_t)(4 * quad) * HW1;
        float s0 = 0.f, s1 = 0.f, s2 = 0.f, s3 = 0.f;
        #pragma unroll 2
        for (int i = lane; i < HW1; i += 32) {
            s0 += __ldcs(p + i);
            s1 += __ldcs(p + HW1 + i);
            s2 += __ldcs(p + 2 * HW1 + i);
            s3 += __ldcs(p + 3 * HW1 + i);
        }
        #pragma unroll
        for (int o = 16; o; o >>= 1) {
            s0 += __shfl_xor_sync(0xffffffffu, s0, o);
            s1 += __shfl_xor_sync(0xffffffffu, s1, o);
            s2 += __shfl_xor_sync(0xffffffffu, s2, o);
            s3 += __shfl_xor_sync(0xffffffffu, s3, o);
        }
        if (lane == 0) {
            const float inv = 1.f / HW1;
            w1[4 * quad]     = s0 * inv;
            w1[4 * quad + 1] = s1 * inv;
            w1[4 * quad + 2] = s2 * inv;
            w1[4 * quad + 3] = s3 * inv;
        }
    }
}

// ---------------------------------------------------------------------------
// Stage 2 (single launch, both levels): per channel-chunk partial
// cam / sumT / sumS.  grid = (3, B, NCH0 + NCH1), block = 256.
// z < NCH0 -> level-0 chunk (float4 path); else level-1 chunk (scalar).
// Block = 128 hw lanes x 2 channel groups; fixed-order combine.
// ---------------------------------------------------------------------------
__global__ __launch_bounds__(256)
void k_cam_all(const float* __restrict__ Tf0, const float* __restrict__ Sf0,
               const float* __restrict__ w0,
               float* __restrict__ pc0, float* __restrict__ pt0, float* __restrict__ ps0,
               const float* __restrict__ Tf1, const float* __restrict__ Sf1,
               const float* __restrict__ w1,
               float* __restrict__ pc1, float* __restrict__ pt1, float* __restrict__ ps1) {
    __shared__ float  sw[64];
    __shared__ float4 red4[3][2][128];   // 12 KB; reused as float[] for level 1

    const int b   = blockIdx.y;
    const int z   = blockIdx.z;
    const int hwl = threadIdx.x & 127;
    const int cg  = threadIdx.x >> 7;    // 0..1

    if (z < NCH0) {
        // ----- level 0: float4 along hw -----
        const int chunk = z;
        for (int i = threadIdx.x; i < CPC0; i += 256)
            sw[i] = w0[b * C0 + chunk * CPC0 + i];
        __syncthreads();

        const int q = blockIdx.x * 128 + hwl;   // float4 index within row
        float4 ac = {0,0,0,0}, at = {0,0,0,0}, as4 = {0,0,0,0};
        if (q < HW4_0) {
            const size_t rb = (size_t)(b * C0 + chunk * CPC0 + cg * CPG0) * HW4_0 + q;
            const float4* tp = reinterpret_cast<const float4*>(Tf0) + rb;
            const float4* sp = reinterpret_cast<const float4*>(Sf0) + rb;
            const float*  wp = sw + cg * CPG0;
            #pragma unroll 8
            for (int c = 0; c < CPG0; ++c) {
                float4 t = __ldcs(tp + (size_t)c * HW4_0);
                float4 s = __ldcs(sp + (size_t)c * HW4_0);
                float  wv = wp[c];
                ac.x = fmaf(wv, t.x, ac.x); ac.y = fmaf(wv, t.y, ac.y);
                ac.z = fmaf(wv, t.z, ac.z); ac.w = fmaf(wv, t.w, ac.w);
                at.x += t.x; at.y += t.y; at.z += t.z; at.w += t.w;
                as4.x += s.x; as4.y += s.y; as4.z += s.z; as4.w += s.w;
            }
        }
        red4[0][cg][hwl] = ac; red4[1][cg][hwl] = at; red4[2][cg][hwl] = as4;
        __syncthreads();

        if (cg == 0 && q < HW4_0) {
            float4 a0 = red4[0][0][hwl], a1 = red4[0][1][hwl];
            float4 t0 = red4[1][0][hwl], t1 = red4[1][1][hwl];
            float4 s0 = red4[2][0][hwl], s1 = red4[2][1][hwl];
            float4 cc = {a0.x+a1.x, a0.y+a1.y, a0.z+a1.z, a0.w+a1.w};
            float4 tt = {t0.x+t1.x, t0.y+t1.y, t0.z+t1.z, t0.w+t1.w};
            float4 ss = {s0.x+s1.x, s0.y+s1.y, s0.z+s1.z, s0.w+s1.w};
            const size_t o = (size_t)(chunk * B + b) * HW4_0 + q;
            reinterpret_cast<float4*>(pc0)[o] = cc;
            reinterpret_cast<float4*>(pt0)[o] = tt;
            reinterpret_cast<float4*>(ps0)[o] = ss;
        }
    } else {
        // ----- level 1: scalar along hw -----
        const int chunk = z - NCH0;
        for (int i = threadIdx.x; i < CPC1; i += 256)
            sw[i] = w1[b * C1 + chunk * CPC1 + i];
        __syncthreads();

        const int hw = blockIdx.x * 128 + hwl;
        float ac = 0.f, at = 0.f, as_ = 0.f;
        if (hw < HW1) {
            const size_t rb = (size_t)(b * C1 + chunk * CPC1 + cg * CPG1) * HW1 + hw;
            const float* tp = Tf1 + rb;
            const float* sp = Sf1 + rb;
            const float* wp = sw + cg * CPG1;
            #pragma unroll 16
            for (int c = 0; c < CPG1; ++c) {
                float t = __ldcs(tp + (size_t)c * HW1);
                float s = __ldcs(sp + (size_t)c * HW1);
                ac = fmaf(wp[c], t, ac);
                at += t;
                as_ += s;
            }
        }
        float* red = reinterpret_cast<float*>(red4);  // [3][2][128] floats
        red[(0*2 + cg)*128 + hwl] = ac;
        red[(1*2 + cg)*128 + hwl] = at;
        red[(2*2 + cg)*128 + hwl] = as_;
        __syncthreads();

        if (cg == 0 && hw < HW1) {
            float cc = red[0*256 + hwl] + red[0*256 + 128 + hwl];
            float tt = red[1*256 + hwl] + red[1*256 + 128 + hwl];
            float ss = red[2*256 + hwl] + red[2*256 + 128 + hwl];
            const size_t o = (size_t)(chunk * B + b) * HW1 + hw;
            pc1[o] = cc; pt1[o] = tt; ps1[o] = ss;
        }
    }
}

// ---------------------------------------------------------------------------
// Stage 3 (single launch): combine chunks + stats + mask + (last block) fw.
// grid = 64 blocks (32 per level), 512 threads.
// ---------------------------------------------------------------------------
template <int C, int HW, int CHUNKS, int PPT>
__device__ __forceinline__
void finish_impl(const float* __restrict__ pc, const float* __restrict__ pt,
                 const float* __restrict__ ps,
                 float* __restrict__ outT, float* __restrict__ outS,
                 float* __restrict__ score_slot, int b,
                 float* smx, float* ssm, float* sthr) {
    constexpr float invC  = 1.f / (float)C;
    constexpr float invHW = 1.f / (float)HW;
    const int t = threadIdx.x;

    float camv[PPT], tv[PPT], sv[PPT];
    float mx = -CUDART_INF_F, sm = 0.f;

    #pragma unroll
    for (int p = 0; p < PPT; ++p) {
        const int i = p * 512 + t;
        camv[p] = 0.f; tv[p] = 0.f; sv[p] = 0.f;
        if (i < HW) {
            float cc = 0.f, tt = 0.f, ss = 0.f;
            #pragma unroll
            for (int ch = 0; ch < CHUNKS; ++ch) {
                const size_t o = (size_t)(ch * B + b) * HW + i;
                cc += pc[o]; tt += pt[o]; ss += ps[o];
            }
            camv[p] = cc;
            tv[p]   = tt * invC;
            sv[p]   = ss * invC;
            mx = fmaxf(mx, cc);
            sm += fmaxf(cc, 0.f);
        }
    }

    smx[t] = mx; ssm[t] = sm;
    __syncthreads();
    #pragma unroll
    for (int s = 256; s; s >>= 1) {
        if (t < s) { smx[t] = fmaxf(smx[t], smx[t + s]); ssm[t] += ssm[t + s]; }
        __syncthreads();
    }
    if (t == 0) {
        *score_slot = ssm[0] * invHW;
        *sthr = fabsf(smx[0] * THRESH);
    }
    __syncthreads();
    const float thr = *sthr;

    #pragma unroll
    for (int p = 0; p < PPT; ++p) {
        const int i = p * 512 + t;
        if (i < HW) {
            const bool m = camv[p] > thr;
            const size_t o = (size_t)b * HW + i;
            outT[o] = m ? tv[p] : 0.f;
            outS[o] = m ? sv[p] : 0.f;
        }
    }
}

__global__ __launch_bounds__(512)
void k_finish_all(const float* __restrict__ pc0, const float* __restrict__ pt0,
                  const float* __restrict__ ps0,
                  const float* __restrict__ pc1, const float* __restrict__ pt1,
                  const float* __restrict__ ps1,
                  float* __restrict__ out, float* __restrict__ score) {
    __shared__ float smx[512], ssm[512], sthr;

    if (blockIdx.x < 32) {
        const int b = blockIdx.x;
        finish_impl<C0, HW0, NCH0, 3>(pc0, pt0, ps0,
                                      out + OFF_ET0, out + OFF_ES0,
                                      score + b, b, smx, ssm, &sthr);
    } else {
        const int b = blockIdx.x - 32;
        finish_impl<C1, HW1, NCH1, 1>(pc1, pt1, ps1,
                                      out + OFF_ET1, out + OFF_ES1,
                                      score + B + b, b, smx, ssm, &sthr);
    }

    // Last block computes feature weights (threadfence + atomic pattern).
    if (threadIdx.x == 0) {
        __threadfence();
        const int old = atomicAdd(&d_cnt, 1);
        if (old == 63) {
            __threadfence();
            float s0 = 0.f, s1 = 0.f;
            for (int i = 0; i < B; ++i) { s0 += score[i]; s1 += score[B + i]; }
            const float inv = 1.f / (s0 + s1);
            out[OFF_FW + 0] = s0 * inv;
            out[OFF_FW + 1] = s1 * inv;
            d_cnt = 0;   // reset for graph replay determinism
        }
    }
}

// ---------------------------------------------------------------------------
extern "C" void kernel_launch(void* const* d_in, const int* in_sizes, int n_in,
                              void* d_out, int out_size) {
    const float* Tf0 = (const float*)d_in[0];
    const float* Tf1 = (const float*)d_in[1];
    const float* Sf0 = (const float*)d_in[2];
    const float* Sf1 = (const float*)d_in[3];
    const float* g0  = (const float*)d_in[4];
    const float* g1  = (const float*)d_in[5];
    float* out = (float*)d_out;

    float *w0, *w1, *pc0, *pt0, *ps0, *pc1, *pt1, *ps1, *score;
    cudaGetSymbolAddress((void**)&w0,  d_w0);
    cudaGetSymbolAddress((void**)&w1,  d_w1);
    cudaGetSymbolAddress((void**)&pc0, d_pc0);
    cudaGetSymbolAddress((void**)&pt0, d_pt0);
    cudaGetSymbolAddress((void**)&ps0, d_ps0);
    cudaGetSymbolAddress((void**)&pc1, d_pc1);
    cudaGetSymbolAddress((void**)&pt1, d_pt1);
    cudaGetSymbolAddress((void**)&ps1, d_ps1);
    cudaGetSymbolAddress((void**)&score, d_score);

    // Stage 1: GradCAM weights, both levels in one launch
    k_gmean_all<<<2048, 256>>>(g0, g1, w0, w1);

    // Stage 2: chunked partial cam / channel sums, both levels in one launch
    {
        dim3 grid(3, B, NCH0 + NCH1);   // 3 x 32 x 24 = 2304 blocks
        k_cam_all<<<grid, 256>>>(Tf0, Sf0, w0, pc0, pt0, ps0,
                                 Tf1, Sf1, w1, pc1, pt1, ps1);
    }

    // Stage 3: combine + stats + mask + fw, one launch
    k_finish_all<<<64, 512>>>(pc0, pt0, ps0, pc1, pt1, ps1, out, score);
}